// round 8
// baseline (speedup 1.0000x reference)
#include <cuda_runtime.h>
#include <math.h>

#define CIN      16
#define COUT     32
#define TAPS     64
#define KDIM     (TAPS * CIN)     // 1024
#define VPB      16               // voxels per block
#define THREADS  256
#define A_STRIDE 1028             // 1024 + 4 pad (rows offset by 4 banks)

// dynamic smem layout:
//  A_s   : VPB * A_STRIDE floats            (65792 B)
//  P_s   : 8 * VPB * COUT floats            (16384 B)
//  St4_s : 8 warps * 32 edges * float4      ( 4096 B)
//  Aux_s : 8 warps * 32 edges * uint        ( 1024 B)
//  den_s : VPB floats                       (   64 B)
#define SMEM_FLOATS (VPB * A_STRIDE + 8 * VPB * COUT + 8 * 32 * 4 + 8 * 32 + VPB)

extern __shared__ float smem[];

__global__ void __launch_bounds__(THREADS, 2)
cconv_kernel(const float* __restrict__ feats,
             const float* __restrict__ inp_points,
             const float* __restrict__ out_points,
             const float* __restrict__ out_extents,
             const float* __restrict__ scale_compat,
             const float* __restrict__ nbr_dist,
             const int*   __restrict__ nbr_idx,
             const int*   __restrict__ row_splits,
             const float* __restrict__ Wg,
             const float* __restrict__ bias,
             float*       __restrict__ out,
             int n_out, int n_edges)
{
    float*  A_s   = smem;
    float*  P_s   = A_s + VPB * A_STRIDE;
    float4* St4_s = reinterpret_cast<float4*>(P_s + 8 * VPB * COUT);
    unsigned int* Aux_s = reinterpret_cast<unsigned int*>(P_s + 8 * VPB * COUT + 8 * 32 * 4);
    float*  den_s = reinterpret_cast<float*>(Aux_s + 8 * 32);

    const int tid  = threadIdx.x;
    const int warp = tid >> 5;
    const int lane = tid & 31;

    float4*       myst  = St4_s + warp * 32;
    unsigned int* myaux = Aux_s + warp * 32;

    // ---- zero both acc rows owned by this warp ----
    {
        float4* acc4 = reinterpret_cast<float4*>(A_s + (warp * 2) * A_STRIDE);
        #pragma unroll
        for (int i = 0; i < 16; ++i)
            acc4[lane + i * 32] = make_float4(0.f, 0.f, 0.f, 0.f);
        if (lane < 8) (A_s + (warp * 2) * A_STRIDE)[2048 + lane] = 0.f;
    }

    // ---- phase 1a: geometry for BOTH voxels in parallel (half-warp each) ----
    const int vhalf = lane >> 4;           // 0 = voxel A, 1 = voxel B
    const int le    = lane & 15;           // edge slot within voxel
    const int vloc  = warp * 2 + vhalf;
    const int v     = blockIdx.x * VPB + vloc;

    float imp_l = 0.f, f0_l = 0.f, f1_l = 0.f, f2_l = 0.f;
    unsigned int aux_l = 0;
    {
        int e0 = 0, cnt = 0;
        if (v < n_out) {
            e0  = row_splits[v];
            cnt = row_splits[v + 1] - e0;
        }
        const bool act = (le < cnt);
        if (v < n_out) {
            const float ox = out_points[v * 3 + 0];
            const float oy = out_points[v * 3 + 1];
            const float oz = out_points[v * 3 + 2];
            const float inv_r = 2.0f / out_extents[v];

            int e = e0 + le;
            if (e >= n_edges) e = n_edges - 1;

            const float sc = scale_compat[e];
            const float d  = nbr_dist[e];
            float omr = 1.0f - d;
            float w6  = omr * omr * omr;
            w6 = fminf(fmaxf(w6, 0.0f), 1.0f);

            const int nb = nbr_idx[e];
            const float rx = (inp_points[nb * 3 + 0] - ox) * inv_r;
            const float ry = (inp_points[nb * 3 + 1] - oy) * inv_r;
            const float rz = (inp_points[nb * 3 + 2] - oz) * inv_r;

            const float l2   = sqrtf(rx * rx + ry * ry + rz * rz);
            const float linf = fmaxf(fabsf(rx), fmaxf(fabsf(ry), fabsf(rz)));
            const float s    = (linf > 0.0f) ? (l2 / fmaxf(linf, 1e-12f)) : 0.0f;

            const float q0 = fminf(fmaxf(rx * s, -1.0f), 1.0f);
            const float q1 = fminf(fmaxf(ry * s, -1.0f), 1.0f);
            const float q2 = fminf(fmaxf(rz * s, -1.0f), 1.0f);

            const float t0 = (q0 + 1.0f) * 1.5f;
            const float t1 = (q1 + 1.0f) * 1.5f;
            const float t2 = (q2 + 1.0f) * 1.5f;

            const float fl0 = fminf(fmaxf(floorf(t0), 0.0f), 2.0f);
            const float fl1 = fminf(fmaxf(floorf(t1), 0.0f), 2.0f);
            const float fl2 = fminf(fmaxf(floorf(t2), 0.0f), 2.0f);
            f0_l = t0 - fl0;
            f1_l = t1 - fl1;
            f2_l = t2 - fl2;
            const int cb = (((int)fl0) * 4 + (int)fl1) * 4 + (int)fl2;

            imp_l = act ? (sc * w6) : 0.f;
            aux_l = ((unsigned int)cb << 18) | (unsigned int)nb;
        }
    }
    myst[lane]  = make_float4(imp_l, f0_l, f1_l, f2_l);
    myaux[lane] = aux_l;

    {
        float den = imp_l;
        #pragma unroll
        for (int off = 8; off > 0; off >>= 1)
            den += __shfl_xor_sync(0xffffffffu, den, off);
        if (le == 0) den_s[vloc] = (den != 0.0f) ? den : 1.0f;
    }
    __syncwarp();

    // ---- phase 1b: scatter, one voxel at a time, full warp ----
    const int ch    = lane & 15;
    const int chalf = lane >> 4;

    #pragma unroll
    for (int vi = 0; vi < 2; ++vi) {
        float* acc = A_s + (warp * 2 + vi) * A_STRIDE;
        const int ebase = vi * 16;

        unsigned int auxr[16];
        float fv[16];
        #pragma unroll
        for (int e = 0; e < 16; ++e) {
            auxr[e] = myaux[ebase + e];
            fv[e] = feats[(auxr[e] & 0x3FFFFu) * CIN + ch];
        }

        #pragma unroll
        for (int e = 0; e < 16; ++e) {
            const float4 g = myst[ebase + e];
            const float psi = g.x * fv[e];
            const int   cb  = (int)(auxr[e] >> 18);
            const float g0 = 1.0f - g.y, g1 = 1.0f - g.z, g2 = 1.0f - g.w;

            #pragma unroll
            for (int cc = 0; cc < 4; ++cc) {
                const int c  = cc * 2 + chalf;
                const int cz = (c >> 2) & 1;
                const int cy = (c >> 1) & 1;
                const int cx = c & 1;
                const float w = (cz ? g.y : g0) * (cy ? g.z : g1) * (cx ? g.w : g2);
                const int corner = cb + cz * 16 + cy * 4 + cx;
                acc[corner * CIN + ch] += w * psi;
            }
        }
    }

    __syncthreads();

    // ---- phase 2: k-split GEMM, scalar FMA.
    //      warp w owns k in [w*128, (w+1)*128).
    //      lane = vq(0..7) + 8*cq(0..3); tile: voxels {vq, vq+8},
    //      couts [8cq, 8cq+8). A via LDS.64, W via LDG.128 (line-dedup'd). ----
    {
        const int kbase = warp * 128;
        const int vq    = lane & 7;
        const int cq    = lane >> 3;
        const float* Wp  = Wg + kbase * COUT + cq * 8;
        const float* Ap0 = A_s + vq * A_STRIDE + kbase;
        const float* Ap1 = A_s + (vq + 8) * A_STRIDE + kbase;

        float acc0[8], acc1[8];
        #pragma unroll
        for (int j = 0; j < 8; ++j) { acc0[j] = 0.f; acc1[j] = 0.f; }

        float2 af[2][2];            // [buf][row]
        float4 wb[2][2][2];         // [buf][krow][half]

        // prologue: chunk 0 (k = 0,1)
        af[0][0] = *reinterpret_cast<const float2*>(Ap0);
        af[0][1] = *reinterpret_cast<const float2*>(Ap1);
        wb[0][0][0] = *reinterpret_cast<const float4*>(Wp);
        wb[0][0][1] = *reinterpret_cast<const float4*>(Wp + 4);
        wb[0][1][0] = *reinterpret_cast<const float4*>(Wp + COUT);
        wb[0][1][1] = *reinterpret_cast<const float4*>(Wp + COUT + 4);

        #pragma unroll 4
        for (int kc = 0; kc < 64; ++kc) {
            const int cur = kc & 1;
            const int nxt = cur ^ 1;
            if (kc < 63) {
                const int koff = (kc + 1) * 2;
                af[nxt][0] = *reinterpret_cast<const float2*>(Ap0 + koff);
                af[nxt][1] = *reinterpret_cast<const float2*>(Ap1 + koff);
                wb[nxt][0][0] = *reinterpret_cast<const float4*>(Wp + koff * COUT);
                wb[nxt][0][1] = *reinterpret_cast<const float4*>(Wp + koff * COUT + 4);
                wb[nxt][1][0] = *reinterpret_cast<const float4*>(Wp + (koff + 1) * COUT);
                wb[nxt][1][1] = *reinterpret_cast<const float4*>(Wp + (koff + 1) * COUT + 4);
            }
            const float a00 = af[cur][0].x, a01 = af[cur][0].y;
            const float a10 = af[cur][1].x, a11 = af[cur][1].y;
            const float* w0 = reinterpret_cast<const float*>(&wb[cur][0][0]);
            const float* w1 = reinterpret_cast<const float*>(&wb[cur][1][0]);
            #pragma unroll
            for (int j = 0; j < 8; ++j) {
                acc0[j] = fmaf(a00, w0[j], acc0[j]);
                acc1[j] = fmaf(a10, w0[j], acc1[j]);
            }
            #pragma unroll
            for (int j = 0; j < 8; ++j) {
                acc0[j] = fmaf(a01, w1[j], acc0[j]);
                acc1[j] = fmaf(a11, w1[j], acc1[j]);
            }
        }

        // store per-warp partials: P_s[warp][v][c]
        float* dst0 = P_s + (warp * VPB + vq) * COUT + cq * 8;
        float* dst1 = P_s + (warp * VPB + vq + 8) * COUT + cq * 8;
        *reinterpret_cast<float4*>(dst0)     = make_float4(acc0[0], acc0[1], acc0[2], acc0[3]);
        *reinterpret_cast<float4*>(dst0 + 4) = make_float4(acc0[4], acc0[5], acc0[6], acc0[7]);
        *reinterpret_cast<float4*>(dst1)     = make_float4(acc1[0], acc1[1], acc1[2], acc1[3]);
        *reinterpret_cast<float4*>(dst1 + 4) = make_float4(acc1[4], acc1[5], acc1[6], acc1[7]);
    }

    __syncthreads();

    // ---- reduce 8 partials, normalize, bias, relu, store ----
    {
        const int vv = tid >> 4;          // 0..15
        const int c0 = (tid & 15) * 2;    // cout pair
        float s0 = 0.f, s1 = 0.f;
        #pragma unroll
        for (int w = 0; w < 8; ++w) {
            const float2 p = *reinterpret_cast<const float2*>(P_s + (w * VPB + vv) * COUT + c0);
            s0 += p.x;
            s1 += p.y;
        }
        const int vg = blockIdx.x * VPB + vv;
        if (vg < n_out) {
            const float inv_den = 1.0f / den_s[vv];
            float y0 = s0 * inv_den + bias[c0 + 0];
            float y1 = s1 * inv_den + bias[c0 + 1];
            float2 r;
            r.x = fmaxf(y0, 0.0f);
            r.y = fmaxf(y1, 0.0f);
            *reinterpret_cast<float2*>(out + vg * COUT + c0) = r;
        }
    }
}

extern "C" void kernel_launch(void* const* d_in, const int* in_sizes, int n_in,
                              void* d_out, int out_size)
{
    const float* feats        = (const float*)d_in[0];
    const float* inp_points   = (const float*)d_in[1];
    const float* out_points   = (const float*)d_in[2];
    const float* out_extents  = (const float*)d_in[3];
    const float* scale_compat = (const float*)d_in[4];
    const float* nbr_dist     = (const float*)d_in[5];
    const int*   nbr_idx      = (const int*)d_in[6];
    const int*   row_splits   = (const int*)d_in[7];
    const float* Wg           = (const float*)d_in[8];
    const float* bias         = (const float*)d_in[9];
    float*       out          = (float*)d_out;

    const int n_out   = in_sizes[7] - 1;
    const int n_edges = in_sizes[6];

    const size_t smem_bytes = SMEM_FLOATS * sizeof(float);
    cudaFuncSetAttribute(cconv_kernel,
                         cudaFuncAttributeMaxDynamicSharedMemorySize,
                         (int)smem_bytes);

    const int grid = (n_out + VPB - 1) / VPB;
    cconv_kernel<<<grid, THREADS, smem_bytes>>>(
        feats, inp_points, out_points, out_extents, scale_compat,
        nbr_dist, nbr_idx, row_splits, Wg, bias, out, n_out, n_edges);
}

// round 9
// speedup vs baseline: 1.0429x; 1.0429x over previous
#include <cuda_runtime.h>
#include <math.h>

#define CIN      16
#define COUT     32
#define TAPS     64
#define KDIM     (TAPS * CIN)     // 1024
#define VPB      16               // voxels per block
#define THREADS  256
#define A_STRIDE 1028             // 1024 + 4 pad (rows offset by 4 banks)

// dynamic smem layout:
//  A_s   : VPB * A_STRIDE floats            (65792 B)
//  P_s   : 8 * VPB * COUT floats            (16384 B)
//  St4_s : 8 warps * 32 edges * float4      ( 4096 B)
//  Aux_s : 8 warps * 32 edges * uint        ( 1024 B)
//  den_s : VPB floats                       (   64 B)
#define SMEM_FLOATS (VPB * A_STRIDE + 8 * VPB * COUT + 8 * 32 * 4 + 8 * 32 + VPB)

extern __shared__ float smem[];

__global__ void __launch_bounds__(THREADS, 2)
cconv_kernel(const float* __restrict__ feats,
             const float* __restrict__ inp_points,
             const float* __restrict__ out_points,
             const float* __restrict__ out_extents,
             const float* __restrict__ scale_compat,
             const float* __restrict__ nbr_dist,
             const int*   __restrict__ nbr_idx,
             const int*   __restrict__ row_splits,
             const float* __restrict__ Wg,
             const float* __restrict__ bias,
             float*       __restrict__ out,
             int n_out, int n_edges)
{
    float*  A_s   = smem;
    float*  P_s   = A_s + VPB * A_STRIDE;
    float4* St4_s = reinterpret_cast<float4*>(P_s + 8 * VPB * COUT);
    unsigned int* Aux_s = reinterpret_cast<unsigned int*>(P_s + 8 * VPB * COUT + 8 * 32 * 4);
    float*  den_s = reinterpret_cast<float*>(Aux_s + 8 * 32);

    const int tid  = threadIdx.x;
    const int warp = tid >> 5;
    const int lane = tid & 31;

    float4*       myst  = St4_s + warp * 32;
    unsigned int* myaux = Aux_s + warp * 32;

    // ---- zero both acc rows owned by this warp ----
    {
        float4* acc4 = reinterpret_cast<float4*>(A_s + (warp * 2) * A_STRIDE);
        #pragma unroll
        for (int i = 0; i < 16; ++i)
            acc4[lane + i * 32] = make_float4(0.f, 0.f, 0.f, 0.f);
        if (lane < 8) (A_s + (warp * 2) * A_STRIDE)[2048 + lane] = 0.f;
    }

    // ---- phase 1a: geometry for BOTH voxels in parallel (half-warp each) ----
    const int vhalf = lane >> 4;           // 0 = voxel A, 1 = voxel B
    const int le    = lane & 15;           // edge slot within voxel
    const int vloc  = warp * 2 + vhalf;
    const int v     = blockIdx.x * VPB + vloc;

    float imp_l = 0.f, f0_l = 0.f, f1_l = 0.f, f2_l = 0.f;
    unsigned int aux_l = 0;
    {
        int e0 = 0, cnt = 0;
        if (v < n_out) {
            e0  = row_splits[v];
            cnt = row_splits[v + 1] - e0;
        }
        const bool act = (le < cnt);
        if (v < n_out) {
            const float ox = out_points[v * 3 + 0];
            const float oy = out_points[v * 3 + 1];
            const float oz = out_points[v * 3 + 2];
            const float inv_r = 2.0f / out_extents[v];

            int e = e0 + le;
            if (e >= n_edges) e = n_edges - 1;

            const float sc = scale_compat[e];
            const float d  = nbr_dist[e];
            float omr = 1.0f - d;
            float w6  = omr * omr * omr;
            w6 = fminf(fmaxf(w6, 0.0f), 1.0f);

            const int nb = nbr_idx[e];
            const float rx = (inp_points[nb * 3 + 0] - ox) * inv_r;
            const float ry = (inp_points[nb * 3 + 1] - oy) * inv_r;
            const float rz = (inp_points[nb * 3 + 2] - oz) * inv_r;

            const float l2   = sqrtf(rx * rx + ry * ry + rz * rz);
            const float linf = fmaxf(fabsf(rx), fmaxf(fabsf(ry), fabsf(rz)));
            const float s    = (linf > 0.0f) ? (l2 / fmaxf(linf, 1e-12f)) : 0.0f;

            const float q0 = fminf(fmaxf(rx * s, -1.0f), 1.0f);
            const float q1 = fminf(fmaxf(ry * s, -1.0f), 1.0f);
            const float q2 = fminf(fmaxf(rz * s, -1.0f), 1.0f);

            const float t0 = (q0 + 1.0f) * 1.5f;
            const float t1 = (q1 + 1.0f) * 1.5f;
            const float t2 = (q2 + 1.0f) * 1.5f;

            const float fl0 = fminf(fmaxf(floorf(t0), 0.0f), 2.0f);
            const float fl1 = fminf(fmaxf(floorf(t1), 0.0f), 2.0f);
            const float fl2 = fminf(fmaxf(floorf(t2), 0.0f), 2.0f);
            f0_l = t0 - fl0;
            f1_l = t1 - fl1;
            f2_l = t2 - fl2;
            const int cb = (((int)fl0) * 4 + (int)fl1) * 4 + (int)fl2;

            imp_l = act ? (sc * w6) : 0.f;
            aux_l = ((unsigned int)cb << 18) | (unsigned int)nb;
        }
    }
    myst[lane]  = make_float4(imp_l, f0_l, f1_l, f2_l);
    myaux[lane] = aux_l;

    {
        float den = imp_l;
        #pragma unroll
        for (int off = 8; off > 0; off >>= 1)
            den += __shfl_xor_sync(0xffffffffu, den, off);
        if (le == 0) den_s[vloc] = (den != 0.0f) ? den : 1.0f;
    }
    __syncwarp();

    // ---- phase 1b: scatter, one voxel at a time, full warp ----
    const int ch    = lane & 15;
    const int chalf = lane >> 4;

    #pragma unroll
    for (int vi = 0; vi < 2; ++vi) {
        float* acc = A_s + (warp * 2 + vi) * A_STRIDE;
        const int ebase = vi * 16;

        unsigned int auxr[16];
        float fv[16];
        #pragma unroll
        for (int e = 0; e < 16; ++e) {
            auxr[e] = myaux[ebase + e];
            fv[e] = feats[(auxr[e] & 0x3FFFFu) * CIN + ch];
        }

        #pragma unroll
        for (int e = 0; e < 16; ++e) {
            const float4 g = myst[ebase + e];
            const float psi = g.x * fv[e];
            const int   cb  = (int)(auxr[e] >> 18);
            const float g0 = 1.0f - g.y, g1 = 1.0f - g.z, g2 = 1.0f - g.w;

            #pragma unroll
            for (int cc = 0; cc < 4; ++cc) {
                const int c  = cc * 2 + chalf;
                const int cz = (c >> 2) & 1;
                const int cy = (c >> 1) & 1;
                const int cx = c & 1;
                const float w = (cz ? g.y : g0) * (cy ? g.z : g1) * (cx ? g.w : g2);
                const int corner = cb + cz * 16 + cy * 4 + cx;
                acc[corner * CIN + ch] += w * psi;
            }
        }
    }

    __syncthreads();

    // ---- phase 2: k-split GEMM, scalar FMA.
    //      warp w owns k in [w*128, (w+1)*128). chunk = 4 k (64 FFMA prefetch depth).
    //      lane = vq(0..7) + 8*cq(0..3); tile: voxels {vq, vq+8},
    //      couts [8cq, 8cq+8). A: 2 LDS.128/chunk (8 distinct rows per phase,
    //      full 128B crossbar). W: 8 LDG.128/chunk (one 128B line each). ----
    {
        const int kbase = warp * 128;
        const int vq    = lane & 7;
        const int cq    = lane >> 3;
        const float* Wp  = Wg + kbase * COUT + cq * 8;
        const float* Ap0 = A_s + vq * A_STRIDE + kbase;
        const float* Ap1 = A_s + (vq + 8) * A_STRIDE + kbase;

        float acc0[8], acc1[8];
        #pragma unroll
        for (int j = 0; j < 8; ++j) { acc0[j] = 0.f; acc1[j] = 0.f; }

        float4 af[2][2];        // [buf][row]  A fragments (k..k+3)
        float4 wl[2][4];        // [buf][j]    W[k+j][cq*8 .. +4)
        float4 wh[2][4];        // [buf][j]    W[k+j][cq*8+4 .. +8)

        // prologue: chunk 0
        af[0][0] = *reinterpret_cast<const float4*>(Ap0);
        af[0][1] = *reinterpret_cast<const float4*>(Ap1);
        #pragma unroll
        for (int j = 0; j < 4; ++j) {
            wl[0][j] = *reinterpret_cast<const float4*>(Wp + j * COUT);
            wh[0][j] = *reinterpret_cast<const float4*>(Wp + j * COUT + 4);
        }

        #pragma unroll 2
        for (int kc = 0; kc < 32; ++kc) {
            const int cur = kc & 1;
            const int nxt = cur ^ 1;
            if (kc < 31) {
                const int koff = (kc + 1) * 4;
                af[nxt][0] = *reinterpret_cast<const float4*>(Ap0 + koff);
                af[nxt][1] = *reinterpret_cast<const float4*>(Ap1 + koff);
                #pragma unroll
                for (int j = 0; j < 4; ++j) {
                    wl[nxt][j] = *reinterpret_cast<const float4*>(Wp + (koff + j) * COUT);
                    wh[nxt][j] = *reinterpret_cast<const float4*>(Wp + (koff + j) * COUT + 4);
                }
            }
            const float* a0 = reinterpret_cast<const float*>(&af[cur][0]);
            const float* a1 = reinterpret_cast<const float*>(&af[cur][1]);
            #pragma unroll
            for (int j = 0; j < 4; ++j) {
                const float* wlo = reinterpret_cast<const float*>(&wl[cur][j]);
                const float* whi = reinterpret_cast<const float*>(&wh[cur][j]);
                #pragma unroll
                for (int p = 0; p < 4; ++p) {
                    acc0[p]     = fmaf(a0[j], wlo[p], acc0[p]);
                    acc1[p]     = fmaf(a1[j], wlo[p], acc1[p]);
                    acc0[p + 4] = fmaf(a0[j], whi[p], acc0[p + 4]);
                    acc1[p + 4] = fmaf(a1[j], whi[p], acc1[p + 4]);
                }
            }
        }

        // store per-warp partials: P_s[warp][v][c]
        float* dst0 = P_s + (warp * VPB + vq) * COUT + cq * 8;
        float* dst1 = P_s + (warp * VPB + vq + 8) * COUT + cq * 8;
        *reinterpret_cast<float4*>(dst0)     = make_float4(acc0[0], acc0[1], acc0[2], acc0[3]);
        *reinterpret_cast<float4*>(dst0 + 4) = make_float4(acc0[4], acc0[5], acc0[6], acc0[7]);
        *reinterpret_cast<float4*>(dst1)     = make_float4(acc1[0], acc1[1], acc1[2], acc1[3]);
        *reinterpret_cast<float4*>(dst1 + 4) = make_float4(acc1[4], acc1[5], acc1[6], acc1[7]);
    }

    __syncthreads();

    // ---- reduce 8 partials, normalize, bias, relu, store ----
    {
        const int vv = tid >> 4;          // 0..15
        const int c0 = (tid & 15) * 2;    // cout pair
        float s0 = 0.f, s1 = 0.f;
        #pragma unroll
        for (int w = 0; w < 8; ++w) {
            const float2 p = *reinterpret_cast<const float2*>(P_s + (w * VPB + vv) * COUT + c0);
            s0 += p.x;
            s1 += p.y;
        }
        const int vg = blockIdx.x * VPB + vv;
        if (vg < n_out) {
            const float inv_den = 1.0f / den_s[vv];
            float y0 = s0 * inv_den + bias[c0 + 0];
            float y1 = s1 * inv_den + bias[c0 + 1];
            float2 r;
            r.x = fmaxf(y0, 0.0f);
            r.y = fmaxf(y1, 0.0f);
            *reinterpret_cast<float2*>(out + vg * COUT + c0) = r;
        }
    }
}

extern "C" void kernel_launch(void* const* d_in, const int* in_sizes, int n_in,
                              void* d_out, int out_size)
{
    const float* feats        = (const float*)d_in[0];
    const float* inp_points   = (const float*)d_in[1];
    const float* out_points   = (const float*)d_in[2];
    const float* out_extents  = (const float*)d_in[3];
    const float* scale_compat = (const float*)d_in[4];
    const float* nbr_dist     = (const float*)d_in[5];
    const int*   nbr_idx      = (const int*)d_in[6];
    const int*   row_splits   = (const int*)d_in[7];
    const float* Wg           = (const float*)d_in[8];
    const float* bias         = (const float*)d_in[9];
    float*       out          = (float*)d_out;

    const int n_out   = in_sizes[7] - 1;
    const int n_edges = in_sizes[6];

    const size_t smem_bytes = SMEM_FLOATS * sizeof(float);
    cudaFuncSetAttribute(cconv_kernel,
                         cudaFuncAttributeMaxDynamicSharedMemorySize,
                         (int)smem_bytes);

    const int grid = (n_out + VPB - 1) / VPB;
    cconv_kernel<<<grid, THREADS, smem_bytes>>>(
        feats, inp_points, out_points, out_extents, scale_compat,
        nbr_dist, nbr_idx, row_splits, Wg, bias, out, n_out, n_edges);
}